// round 2
// baseline (speedup 1.0000x reference)
#include <cuda_runtime.h>
#include <cuda_bf16.h>
#include <cstdint>

// ---------------- Problem dims ----------------
#define B_SZ   256
#define T_LEN  1024
#define I_DIM  64
#define H_DIM  256
#define KX     320            // 256 (h) + 64 (x_t) unified K
#define NBG    16             // batch groups
#define NGG    8              // gate groups (CTAs per batch group)
#define WPAD   132            // padded row stride (floats) for weight tile
#define GP     132            // padded gate-spill stride

#define SMEM_FLOATS (KX*WPAD + KX*16 + 16*GP + 512)
#define SMEM_BYTES  (SMEM_FLOATS * 4)

// ---------------- Static device scratch (allowed) ----------------
__device__ float        g_xT[T_LEN][NBG][I_DIM][16];     // 64 MB: x transposed k-major
__device__ float        g_HT[2][NBG][H_DIM][16];         // ping-pong hidden, k-major
__device__ unsigned int g_cnt[NBG * 32];                 // per-group arrival counters

// ---------------- f32x2 helpers ----------------
__device__ __forceinline__ unsigned long long ffma2(unsigned long long a,
                                                    unsigned long long b,
                                                    unsigned long long c) {
  unsigned long long d;
  asm("fma.rn.f32x2 %0, %1, %2, %3;" : "=l"(d) : "l"(a), "l"(b), "l"(c));
  return d;
}
__device__ __forceinline__ unsigned long long packdup(float v) {
  unsigned long long d;
  asm("mov.b64 %0, {%1, %2};" : "=l"(d) : "f"(v), "f"(v));
  return d;
}

__device__ __forceinline__ float fsig(float x) {
  x = fminf(fmaxf(x, -15.0f), 15.0f);
  return __fdividef(1.0f, 1.0f + __expf(-x));
}
__device__ __forceinline__ float ftanh(float x) {
  x = fminf(fmaxf(x, -15.0f), 15.0f);
  float e = __expf(-2.0f * x);
  return __fdividef(1.0f - e, 1.0f + e);
}

// ---------------- Kernels ----------------
__global__ void reset_kernel() {
  if (threadIdx.x < NBG * 32) g_cnt[threadIdx.x] = 0u;
}

// x [B][T][I] -> g_xT [T][bg][j][bl]   (read-coalesced, scattered writes)
__global__ void xt_kernel(const float* __restrict__ x) {
  long long i = (long long)blockIdx.x * 256 + threadIdx.x;  // 16,777,216 elems
  int j = (int)(i & 63);
  int t = (int)((i >> 6) & 1023);
  int b = (int)(i >> 16);
  g_xT[t][b >> 4][j][b & 15] = x[i];
}

__global__ void __launch_bounds__(256, 1) lstm_kernel(
    const float* __restrict__ W_ih,
    const float* __restrict__ W_hh,
    const float* __restrict__ b_ih,
    const float* __restrict__ b_hh) {
  extern __shared__ float smem[];
  float* Wsm = smem;                   // [KX][WPAD] weight slice, k-major
  float* hsm = Wsm + KX * WPAD;        // [KX][16]   extended input, k-major
  float* gsm = hsm + KX * 16;          // [16][GP]   gate pre-activations
  float* csm = gsm + 16 * GP;          // [16][32]   cell state (b*32+col)

  const int tid = threadIdx.x;
  const int bg  = blockIdx.x >> 3;
  const int gg  = blockIdx.x & 7;
  const int c0  = gg * 32;

  // ---- one-time: weight slice -> smem, gate rows regrouped ----
  // local row r: gate gt = r>>5, col = r&31 -> global row gt*H + c0 + col
  for (int i = tid; i < 128 * H_DIM; i += 256) {
    int r = i >> 8, k = i & 255;
    int gr = (r >> 5) * H_DIM + c0 + (r & 31);
    Wsm[k * WPAD + r] = W_hh[gr * H_DIM + k];
  }
  for (int i = tid; i < 128 * I_DIM; i += 256) {
    int r = i >> 6, k = i & 63;
    int gr = (r >> 5) * H_DIM + c0 + (r & 31);
    Wsm[(H_DIM + k) * WPAD + r] = W_ih[gr * I_DIM + k];
  }
  csm[tid] = 0.0f;
  csm[tid + 256] = 0.0f;

  // K-loop mapping: thread = 4 rows x 2 batch
  const int rg = tid >> 3;  // 0..31 -> rows rg*4 .. rg*4+3
  const int bp = tid & 7;   // batch pair: b = 2bp, 2bp+1

  // epilogue mapping: thread = 1 col x 2 batch
  const int ecol = tid & 31;
  const int ebq  = tid >> 5;  // handles b = ebq and ebq+8

  float bias[4];
#pragma unroll
  for (int g = 0; g < 4; g++) {
    int gr = g * H_DIM + c0 + ecol;
    bias[g] = b_ih[gr] + b_hh[gr];
  }

  volatile unsigned int* cnt = &g_cnt[bg * 32];

  for (int t = 0; t < T_LEN; t++) {
    // ---- fill hsm: k<256 = h_t (k-major copy), k>=256 = x_t ----
    if (t == 0) {
      for (int i = tid; i < H_DIM * 16; i += 256) hsm[i] = 0.0f;
    } else {
      const float4* src = (const float4*)&g_HT[t & 1][bg][0][0];
      float4* dst = (float4*)hsm;
#pragma unroll
      for (int i = 0; i < 4; i++) dst[tid + i * 256] = __ldcg(src + tid + i * 256);
    }
    ((float4*)(hsm + H_DIM * 16))[tid] =
        __ldcg((const float4*)&g_xT[t][bg][0][0] + tid);
    __syncthreads();

    // ---- gates = W_slice @ [h; x_t]  (f32x2 over adjacent rows) ----
    unsigned long long acc00 = 0, acc01 = 0, acc10 = 0, acc11 = 0;
    const float* wp = Wsm + rg * 4;
    const float* hp = hsm + bp * 2;
#pragma unroll 8
    for (int k = 0; k < KX; k++) {
      ulonglong2 w2 = *(const ulonglong2*)(wp + k * WPAD);
      float2 h2 = *(const float2*)(hp + k * 16);
      unsigned long long hd0 = packdup(h2.x);
      unsigned long long hd1 = packdup(h2.y);
      acc00 = ffma2(w2.x, hd0, acc00);
      acc01 = ffma2(w2.y, hd0, acc01);
      acc10 = ffma2(w2.x, hd1, acc10);
      acc11 = ffma2(w2.y, hd1, acc11);
    }
    {
      int b = bp * 2;
      ulonglong2 s0; s0.x = acc00; s0.y = acc01;
      ulonglong2 s1; s1.x = acc10; s1.y = acc11;
      *(ulonglong2*)(gsm + b * GP + rg * 4)       = s0;
      *(ulonglong2*)(gsm + (b + 1) * GP + rg * 4) = s1;
    }
    __syncthreads();

    // ---- epilogue: activations + c/h update (CTA-local) ----
#pragma unroll
    for (int u = 0; u < 2; u++) {
      int b = ebq + u * 8;
      float gi = gsm[b * GP +  0 + ecol] + bias[0];
      float gf = gsm[b * GP + 32 + ecol] + bias[1];
      float gc = gsm[b * GP + 64 + ecol] + bias[2];
      float go = gsm[b * GP + 96 + ecol] + bias[3];
      float iv = fsig(gi), fv = fsig(gf), cv = ftanh(gc), ov = fsig(go);
      float cnew = fv * csm[b * 32 + ecol] + iv * cv;
      csm[b * 32 + ecol] = cnew;
      float h = ov * ftanh(cnew);
      __stcg(&g_HT[(t + 1) & 1][bg][c0 + ecol][b], h);
    }
    __threadfence();
    __syncthreads();
    if (tid == 0) {
      atomicAdd((unsigned int*)&g_cnt[bg * 32], 1u);
      unsigned int target = (unsigned int)(NGG * (t + 1));
      while (*cnt < target) __nanosleep(32);
      __threadfence();
    }
    __syncthreads();
  }
}

// out[b] = h_last . fc_w + fc_b   (h_last is in g_HT[0] after t=1023)
__global__ void fc_kernel(const float* __restrict__ fc_w,
                          const float* __restrict__ fc_b,
                          float* __restrict__ out) {
  int b = threadIdx.x;             // 0..255
  int bg = b >> 4, bl = b & 15;
  float s = 0.0f;
#pragma unroll 8
  for (int col = 0; col < H_DIM; col++)
    s += g_HT[0][bg][col][bl] * fc_w[col];
  out[b] = s + fc_b[0];
}

// ---------------- Launch ----------------
extern "C" void kernel_launch(void* const* d_in, const int* in_sizes, int n_in,
                              void* d_out, int out_size) {
  const float* x    = (const float*)d_in[0];
  const float* W_ih = (const float*)d_in[1];
  const float* W_hh = (const float*)d_in[2];
  const float* b_ih = (const float*)d_in[3];
  const float* b_hh = (const float*)d_in[4];
  const float* fc_w = (const float*)d_in[5];
  const float* fc_b = (const float*)d_in[6];
  float* out = (float*)d_out;

  static bool attr_set = false;
  if (!attr_set) {
    cudaFuncSetAttribute(lstm_kernel,
                         cudaFuncAttributeMaxDynamicSharedMemorySize, SMEM_BYTES);
    attr_set = true;
  }

  reset_kernel<<<1, 512>>>();
  xt_kernel<<<(B_SZ * T_LEN * I_DIM) / 256, 256>>>(x);
  lstm_kernel<<<NBG * NGG, 256, SMEM_BYTES>>>(W_ih, W_hh, b_ih, b_hh);
  fc_kernel<<<1, 256>>>(fc_w, fc_b, out);
}